// round 15
// baseline (speedup 1.0000x reference)
#include <cuda_runtime.h>
#include <math.h>

typedef unsigned long long ull;

// Problem constants (fixed shapes)
#define Bb 32
#define Cc 3
#define Hh 256
#define Ww 832
#define HWsz (Hh*Ww)          // 212992
#define BC (Bb*Cc)            // 96
#define KDET 100
#define QPR (Ww/4)            // 208 float4-quads per row
#define QPS (Hh*QPR)          // 53248 quads per slice

#define NMS_T 512
#define NWARP (NMS_T / 32)    // 16
#define QPT 8                 // quads per thread
#define CHUNK (NMS_T * QPT)   // 4096 quads per block
#define BLK_PER_SLICE (QPS / CHUNK)   // 13

// Fast-path value filter: survivors below T0F cannot be in the per-slice top-100
// WHENEVER the count of survivors >= T0F is itself >= 100 (all kept keys dominate
// all dropped keys). select_topk verifies the count and falls back to an exact
// full rebuild otherwise. For this input: ~3.1K >= T0F per slice vs K=100 (31x).
#define T0F 0.984375f

#define PI_F 3.14159265358979323846f
#define HALF_PI_F 1.57079632679489661923f

// ---------------- scratch (device globals; no runtime allocation) ----------------
__device__ ull g_cand[(size_t)BC * HWsz];     // per-slice contiguous candidate list
__device__ int g_cnt[BC];                     // per-slice count (reset by select epilogue)
__device__ ull g_top1[BC * KDET];             // per-(b,c) top-100 keys

// key layout: [63:32] = float bits of value (value >= 0 so monotonic as uint)
//             [31:0]  = 0xFFFFFFFF - pixel_index  (larger = smaller index)
// descending key order == jax top_k order (desc value, stable lower-index-first)
__device__ __forceinline__ ull make_key(float v, unsigned pix) {
    return ((ull)__float_as_uint(v) << 32) | (ull)(0xFFFFFFFFu - pix);
}

__device__ __forceinline__ float fmax3(float a, float b, float c) {
    return fmaxf(a, fmaxf(b, c));
}

// 3x3 NMS check for one quad at (y, x4); returns 4-bit survivor mask.
__device__ __forceinline__ unsigned nms_quad(const float* __restrict__ rowc,
                                             float4 f, int y, int x4) {
    const float ninf = __int_as_float(0xff800000);
    unsigned mb = 0;
    float lc = (x4 > 0)      ? rowc[x4 - 1] : ninf;
    float rc = (x4 + 4 < Ww) ? rowc[x4 + 4] : ninf;
    float4 fa; float la, ra;
    if (y > 0) {
        const float* rowa = rowc - Ww;
        fa = *(const float4*)(rowa + x4);
        la = (x4 > 0)      ? rowa[x4 - 1] : ninf;
        ra = (x4 + 4 < Ww) ? rowa[x4 + 4] : ninf;
    } else { fa = make_float4(ninf, ninf, ninf, ninf); la = ra = ninf; }
    float4 fb; float lb, rb;
    if (y + 1 < Hh) {
        const float* rowb = rowc + Ww;
        fb = *(const float4*)(rowb + x4);
        lb = (x4 > 0)      ? rowb[x4 - 1] : ninf;
        rb = (x4 + 4 < Ww) ? rowb[x4 + 4] : ninf;
    } else { fb = make_float4(ninf, ninf, ninf, ninf); lb = rb = ninf; }

    float cm0 = fmax3(la, lc, lb);
    float cm1 = fmax3(fa.x, f.x, fb.x);
    float cm2 = fmax3(fa.y, f.y, fb.y);
    float cm3 = fmax3(fa.z, f.z, fb.z);
    float cm4 = fmax3(fa.w, f.w, fb.w);
    float cm5 = fmax3(ra, rc, rb);

    if (f.x >= T0F && f.x >= fmax3(cm0, cm1, cm2)) mb |= 1u;
    if (f.y >= T0F && f.y >= fmax3(cm1, cm2, cm3)) mb |= 2u;
    if (f.z >= T0F && f.z >= fmax3(cm2, cm3, cm4)) mb |= 4u;
    if (f.w >= T0F && f.w >= fmax3(cm3, cm4, cm5)) mb |= 8u;
    return mb;
}

// ---------------- kernel 1: batched-load 3x3 NMS, 8 quads/thread ----------------
__global__ void nms_collect(const float* __restrict__ hm) {
    __shared__ int wsum[NWARP];
    __shared__ int wbase[NWARP];
    __shared__ int s_gbase;

    int tid = threadIdx.x;
    unsigned lane = tid & 31u;
    int wid = tid >> 5;

    int slice = blockIdx.y;
    int q0    = blockIdx.x * CHUNK + tid;      // quads q0 + i*NMS_T, i in [0,8)
    const float* base = hm + (size_t)slice * HWsz;

    // phase 1: batch all 8 independent 128-bit loads (MLP = 8)
    float4 f[QPT];
#pragma unroll
    for (int i = 0; i < QPT; i++) {
        int q  = q0 + i * NMS_T;
        int y  = q / QPR;
        int x4 = (q - y * QPR) * 4;
        f[i] = *(const float4*)(base + y * Ww + x4);
    }

    // phase 2: branchless filter mask
    unsigned fm = 0;
#pragma unroll
    for (int i = 0; i < QPT; i++) {
        float qm = fmaxf(fmaxf(f[i].x, f[i].y), fmaxf(f[i].z, f[i].w));
        if (qm >= T0F) fm |= 1u << i;
    }

    // phase 3: rare full 3x3 checks (values already in registers)
    unsigned mask32 = 0;
    if (fm) {
#pragma unroll
        for (int i = 0; i < QPT; i++) {
            if (fm & (1u << i)) {
                int q  = q0 + i * NMS_T;
                int y  = q / QPR;
                int x4 = (q - y * QPR) * 4;
                mask32 |= nms_quad(base + y * Ww, f[i], y, x4) << (i * 4);
            }
        }
    }

    int cnt = __popc(mask32);

    // block-wide exclusive scan (order canonicalized later by the full sort)
    int inc = cnt;
#pragma unroll
    for (int d = 1; d < 32; d <<= 1) {
        int o = __shfl_up_sync(0xffffffffu, inc, d);
        if ((int)lane >= d) inc += o;
    }
    if (lane == 31) wsum[wid] = inc;
    __syncthreads();
    if (wid == 0) {
        int s = (lane < NWARP) ? wsum[lane] : 0;
#pragma unroll
        for (int d = 1; d < NWARP; d <<= 1) {
            int o = __shfl_up_sync(0xffffffffu, s, d);
            if ((int)lane >= d) s += o;
        }
        if (lane < NWARP) wbase[lane] = s - wsum[lane];
        if (lane == NWARP - 1) s_gbase = s ? atomicAdd(&g_cnt[slice], s) : 0;
    }
    __syncthreads();

    if (mask32) {
        int off = s_gbase + wbase[wid] + (inc - cnt);
        ull* dst = g_cand + (size_t)slice * HWsz;
#pragma unroll
        for (int i = 0; i < QPT; i++) {
            unsigned mb = (mask32 >> (i * 4)) & 0xFu;
            if (!mb) continue;
            int q  = q0 + i * NMS_T;
            int y  = q / QPR;
            int x4 = (q - y * QPR) * 4;
            unsigned pbase = (unsigned)(y * Ww + x4);
            if (mb & 1u) dst[off++] = make_key(f[i].x, pbase + 0);
            if (mb & 2u) dst[off++] = make_key(f[i].y, pbase + 1);
            if (mb & 4u) dst[off++] = make_key(f[i].z, pbase + 2);
            if (mb & 8u) dst[off++] = make_key(f[i].w, pbase + 3);
        }
    }
}

// ---------------- bitonic sort (descending) ----------------
template <int M>
__device__ void bitonic_desc(ull* buf, int tid, int nt) {
    for (int k = 2; k <= M; k <<= 1) {
        for (int j = k >> 1; j > 0; j >>= 1) {
            for (int i = tid; i < M; i += nt) {
                int ij = i ^ j;
                if (ij > i) {
                    bool dir = ((i & k) == 0);          // true -> descending segment
                    ull a = buf[i], b = buf[ij];
                    if ((a < b) == dir) { buf[i] = b; buf[ij] = a; }
                }
            }
            __syncthreads();
        }
    }
}

// ---------------- kernel 2: per-slice exact top-100, leveled 12-bit radix ----------------
__global__ void select_topk(const float* __restrict__ hm) {
    __shared__ int hist[4096];
    __shared__ ull buf[2048];
    __shared__ int wsc[NWARP];
    __shared__ int s_bin, s_pre, s_mexp, s_m;

    int bc  = blockIdx.x;
    int tid = threadIdx.x;
    const int nt = 512;
    unsigned lane = tid & 31u;
    int wid = tid >> 5;

    int n = g_cnt[bc];
    ull* cand = g_cand + (size_t)bc * HWsz;

    // ---- exact fallback: too few fast candidates -> rebuild ALL survivors inline.
    // (Never executes for this input: fast count ~3.1K >> 100.)
    if (n < KDET) {
        if (tid == 0) s_m = 0;
        __syncthreads();
        const float* base = hm + (size_t)bc * HWsz;
        for (int p = tid; p < HWsz; p += nt) {
            float v = base[p];
            int y = p / Ww, x = p - y * Ww;
            bool sv = true;
#pragma unroll
            for (int dy = -1; dy <= 1; dy++)
#pragma unroll
                for (int dx = -1; dx <= 1; dx++) {
                    if ((dy | dx) == 0) continue;
                    int yy = y + dy, xx = x + dx;
                    if ((unsigned)yy < (unsigned)Hh && (unsigned)xx < (unsigned)Ww)
                        sv = sv && (v >= base[yy * Ww + xx]);
                }
            if (sv) { int o = atomicAdd(&s_m, 1); cand[o] = make_key(v, (unsigned)p); }
        }
        __syncthreads();
        n = s_m;
        __syncthreads();
    }
    if (tid == 0) s_m = 0;

    // ---- leveled 12-bit radix: find pref with |{k >= pref}| in [K, 2048]
    ull pref = 0;
    int prevcum = 0;
    int shift = 52;
#pragma unroll 1
    for (int level = 0; level < 4; level++) {
        for (int i = tid; i < 4096; i += nt) hist[i] = 0;
        if (tid == 0) { s_bin = 0; s_pre = prevcum; s_mexp = prevcum; }
        __syncthreads();

        bool top = (level == 0);
        for (int i = tid; i < n; i += nt) {
            ull k = cand[i];
            if (top || ((k >> (shift + 12)) == (pref >> (shift + 12))))
                atomicAdd(&hist[(int)((k >> shift) & 4095)], 1);
        }
        __syncthreads();

        // parallel suffix scan: thread t owns descending chunk of 8 bins
        int lo = 4096 - 8 * (tid + 1);
        int cs = 0;
#pragma unroll
        for (int j = 0; j < 8; j++) cs += hist[lo + j];
        int inc = cs;
#pragma unroll
        for (int d = 1; d < 32; d <<= 1) {
            int o = __shfl_up_sync(0xffffffffu, inc, d);
            if ((int)lane >= d) inc += o;
        }
        if (lane == 31) wsc[wid] = inc;
        __syncthreads();
        int wpre = 0;
        {
            int s = (lane < NWARP) ? wsc[lane] : 0;
#pragma unroll
            for (int d = 1; d < NWARP; d <<= 1) {
                int o = __shfl_up_sync(0xffffffffu, s, d);
                if ((int)lane >= d) s += o;
            }
            s = __shfl_sync(0xffffffffu, s, (wid == 0) ? 0 : (wid - 1));
            wpre = (wid == 0) ? 0 : s;
        }
        int pre = prevcum + wpre + (inc - cs);
        if (pre < KDET && pre + cs >= KDET) {     // exactly one crossing thread
            int cum = pre;
            for (int j = 7; j >= 0; j--) {
                int bin = lo + j;
                int c = hist[bin];
                if (cum + c >= KDET) { s_bin = bin; s_pre = cum; s_mexp = cum + c; break; }
                cum += c;
            }
        }
        __syncthreads();
        pref |= ((ull)s_bin) << shift;
        prevcum = s_pre;
        int mexp = s_mexp;
        __syncthreads();
        if (mexp <= 2048 || shift == 16) break;
        shift -= 12;
    }

    // ---- single collect pass + sort
    for (int i = tid; i < n; i += nt) {
        ull k = cand[i];
        if (k >= pref) {
            int p = atomicAdd(&s_m, 1);
            if (p < 2048) buf[p] = k;
        }
    }
    __syncthreads();
    int m = min(s_m, 2048);

    if (m <= 512) {
        for (int i = tid + m; i < 512; i += nt) buf[i] = 0xFFFFFFFFull;  // value 0, pix 0
        __syncthreads();
        bitonic_desc<512>(buf, tid, nt);
    } else {
        for (int i = tid + m; i < 2048; i += nt) buf[i] = 0xFFFFFFFFull;
        __syncthreads();
        bitonic_desc<2048>(buf, tid, nt);
    }

    if (tid < KDET) g_top1[bc * KDET + tid] = buf[tid];

    // epilogue: reset counter for the next graph replay
    if (tid == 0) g_cnt[bc] = 0;
}

// ---------------- kernel 3: per-batch 3-way merge-rank + geometry epilogue ----------------
// Three per-class top-100 lists are sorted descending. Global rank of candidate i =
// own index + (# strictly-greater keys in the other lists via binary search). Re-keyed
// 64-bit keys are pairwise distinct => ranks form a permutation == jax top_k order.
__global__ void finalize(const float* __restrict__ reg,
                         const float* __restrict__ trans,
                         const float* __restrict__ Kmat,
                         const float* __restrict__ size2,
                         const float* __restrict__ hcam,
                         const float* __restrict__ dimsIn,
                         float* __restrict__ out) {
    __shared__ ull s_key[3 * KDET];

    int b = blockIdx.x, tid = threadIdx.x;

    unsigned pix = 0;
    if (tid < 3 * KDET) {
        ull k1 = g_top1[b * (3 * KDET) + tid];   // tid = c*100 + j
        pix = 0xFFFFFFFFu - (unsigned)(k1 & 0xFFFFFFFFu);
        if (pix >= (unsigned)HWsz) pix = 0;
        // re-key with flattened C*K position for the second-stage tie-break
        s_key[tid] = (k1 & 0xFFFFFFFF00000000ull) |
                     (ull)(0xFFFFFFFFu - (unsigned)tid);
    }
    __syncthreads();

    if (tid < 3 * KDET) {
        // own regression gathers (issued early; high MLP overlaps the ranking)
        const float* rb = reg + (size_t)b * 4 * HWsz;
        float dv_delta = rb[0 * HWsz + pix];
        float off_u    = rb[1 * HWsz + pix];
        float ori0     = rb[2 * HWsz + pix];
        float ori1     = rb[3 * HWsz + pix];

        ull x = s_key[tid];
        int a = tid / KDET;
        int r = tid - a * KDET;                  // own-list index
#pragma unroll
        for (int L = 0; L < 3; L++) {
            if (L == a) continue;
            const ull* Ls = s_key + L * KDET;
            int lo = 0, hi = KDET;
            while (lo < hi) {                    // count of keys > x (descending list)
                int mid = (lo + hi) >> 1;
                if (Ls[mid] > x) lo = mid + 1; else hi = mid;
            }
            r += lo;
        }

        if (r < KDET) {
            float score = __uint_as_float((unsigned)(x >> 32));
            int clsI = a;

            int ysI = pix / Ww;
            int xsI = pix - ysI * Ww;
            float xs = (float)xsI, ys = (float)ysI;

            // 3x3 inverse of trans_mat (first row needed for img_x)
            const float* T = trans + b * 9;
            float a00=T[0],a01=T[1],a02=T[2],a10=T[3],a11=T[4],a12=T[5],a20=T[6],a21=T[7],a22=T[8];
            float det = a00*(a11*a22 - a12*a21) - a01*(a10*a22 - a12*a20) + a02*(a10*a21 - a11*a20);
            float id = 1.0f / det;
            float i00=(a11*a22-a12*a21)*id, i01=(a02*a21-a01*a22)*id, i02=(a01*a12-a02*a11)*id;

            float ptx = xs + off_u, pty = ys;
            float img_x = i00*ptx + i01*pty + i02;

            const float* Km = Kmat + b * 9;
            float fx = Km[0], cxk = Km[2], fy = Km[4];

            float h = hcam[b];
            float d0 = dimsIn[b*3+0], d1 = dimsIn[b*3+1], d2 = dimsIn[b*3+2];
            if (!isfinite(d0)) d0 = 3.88f;
            if (!isfinite(d1)) d1 = 1.63f;
            if (!isfinite(d2)) d2 = 1.53f;

            float h_ref = h - d1 * 0.5f;
            float fyh = fy * fabsf(h_ref);
            float log_dv_ref = logf(fmaxf(fyh, 1e-7f) / 28.01f);
            float log_dv = fminf(fmaxf(log_dv_ref + dv_delta, -4.0f), 8.0f);
            float depth = fminf(fmaxf(fyh * expf(-log_dv), 0.5f), 120.0f);
            float pxl = (img_x - cxk) * depth / fx;

            float ray = atanf(pxl / (depth + 1e-7f));
            float alpha = atanf(ori0 / (ori1 + 1e-7f)) + (ori1 >= 0.0f ? -HALF_PI_F : HALF_PI_F);
            float roty = alpha + ray;
            if (roty >  PI_F) roty -= 2.0f * PI_F;
            if (roty < -PI_F) roty += 2.0f * PI_F;
            float cs = cosf(roty), sn = sinf(roty);

            const float cx8[8] = {-0.5f, 0.5f, 0.5f, 0.5f, 0.5f,-0.5f,-0.5f,-0.5f};
            const float cy8[8] = {-1.0f,-1.0f, 0.0f, 0.0f,-1.0f,-1.0f, 0.0f, 0.0f};
            const float cz8[8] = {-0.5f,-0.5f,-0.5f, 0.5f, 0.5f, 0.5f, 0.5f,-0.5f};

            float umin =  3.4e38f, umax = -3.4e38f, vmin = 3.4e38f, vmax = -3.4e38f;
#pragma unroll
            for (int i = 0; i < 8; i++) {
                float xc = d0 * cx8[i], yc = d1 * cy8[i], zc = d2 * cz8[i];
                float bx =  cs * xc + sn * zc + pxl;
                float by =  yc + h;
                float bz = -sn * xc + cs * zc + depth;
                float up = Km[0]*bx + Km[1]*by + Km[2]*bz;
                float vp = Km[3]*bx + Km[4]*by + Km[5]*bz;
                float wp = Km[6]*bx + Km[7]*by + Km[8]*bz;
                float u = up / wp, v = vp / wp;
                umin = fminf(umin, u); umax = fmaxf(umax, u);
                vmin = fminf(vmin, v); vmax = fmaxf(vmax, v);
            }
            float img_w = size2[0], img_h = size2[1];
            float xmin = fminf(fmaxf(umin, 0.0f), img_w);
            float xmax = fminf(fmaxf(umax, 0.0f), img_w);
            float ymin = fminf(fmaxf(vmin, 0.0f), img_h);
            float ymax = fminf(fmaxf(vmax, 0.0f), img_h);

            float keep = (score > 0.25f) ? 1.0f : 0.0f;

            float o[14];
            o[0]  = (float)clsI;
            o[1]  = alpha;
            o[2]  = xmin; o[3] = ymin; o[4] = xmax; o[5] = ymax;
            o[6]  = d1;   o[7] = d2;   o[8] = d0;          // roll(dims, -1)
            o[9]  = pxl;  o[10] = h;   o[11] = depth;
            o[12] = roty;
            o[13] = score;

            float* dst = out + (size_t)(b * KDET + r) * 14;
#pragma unroll
            for (int c = 0; c < 14; c++) dst[c] = o[c] * keep;
        }
    }
}

// ---------------- launch ----------------
extern "C" void kernel_launch(void* const* d_in, const int* in_sizes, int n_in,
                              void* d_out, int out_size) {
    const float* hm    = (const float*)d_in[0];
    const float* reg   = (const float*)d_in[1];
    const float* trans = (const float*)d_in[2];
    const float* Kmat  = (const float*)d_in[3];
    const float* size2 = (const float*)d_in[4];
    const float* hcam  = (const float*)d_in[5];
    const float* dims  = (const float*)d_in[6];
    float* out = (float*)d_out;

    dim3 grid(BLK_PER_SLICE, BC);              // (13, 96)
    nms_collect<<<grid, NMS_T>>>(hm);
    select_topk<<<BC, 512>>>(hm);
    finalize<<<Bb, 320>>>(reg, trans, Kmat, size2, hcam, dims, out);
}

// round 16
// speedup vs baseline: 1.1289x; 1.1289x over previous
#include <cuda_runtime.h>
#include <math.h>

typedef unsigned long long ull;

// Problem constants (fixed shapes)
#define Bb 32
#define Cc 3
#define Hh 256
#define Ww 832
#define HWsz (Hh*Ww)          // 212992
#define BC (Bb*Cc)            // 96
#define KDET 100
#define QPR (Ww/4)            // 208 float4-quads per row
#define QPS (Hh*QPR)          // 53248 quads per slice

#define NMS_T 512
#define NWARP (NMS_T / 32)    // 16
#define QPT 4                 // quads per thread
#define CHUNK (NMS_T * QPT)   // 2048 quads per block
#define BLK_PER_SLICE (QPS / CHUNK)   // 26

// Fast-path value filter: survivors below T0F cannot be in the per-slice top-100
// WHENEVER the count of survivors >= T0F is itself >= 100 (all kept keys dominate
// all dropped keys). select_topk verifies the count and falls back to an exact
// full rebuild otherwise. For this input: ~3.1K >= T0F per slice vs K=100 (31x).
#define T0F 0.984375f

#define PI_F 3.14159265358979323846f
#define HALF_PI_F 1.57079632679489661923f

// ---------------- scratch (device globals; no runtime allocation) ----------------
__device__ ull g_cand[(size_t)BC * HWsz];     // per-slice contiguous candidate list
__device__ int g_cnt[BC];                     // per-slice count (reset by select epilogue)
__device__ ull g_top1[BC * KDET];             // per-(b,c) top-100 keys

// key layout: [63:32] = float bits of value (value >= 0 so monotonic as uint)
//             [31:0]  = 0xFFFFFFFF - pixel_index  (larger = smaller index)
// descending key order == jax top_k order (desc value, stable lower-index-first)
__device__ __forceinline__ ull make_key(float v, unsigned pix) {
    return ((ull)__float_as_uint(v) << 32) | (ull)(0xFFFFFFFFu - pix);
}

__device__ __forceinline__ float fmax3(float a, float b, float c) {
    return fmaxf(a, fmaxf(b, c));
}

// 3x3 NMS check for one quad at (y, x4); returns 4-bit survivor mask.
__device__ __forceinline__ unsigned nms_quad(const float* __restrict__ rowc,
                                             float4 f, int y, int x4) {
    const float ninf = __int_as_float(0xff800000);
    unsigned mb = 0;
    float lc = (x4 > 0)      ? rowc[x4 - 1] : ninf;
    float rc = (x4 + 4 < Ww) ? rowc[x4 + 4] : ninf;
    float4 fa; float la, ra;
    if (y > 0) {
        const float* rowa = rowc - Ww;
        fa = *(const float4*)(rowa + x4);
        la = (x4 > 0)      ? rowa[x4 - 1] : ninf;
        ra = (x4 + 4 < Ww) ? rowa[x4 + 4] : ninf;
    } else { fa = make_float4(ninf, ninf, ninf, ninf); la = ra = ninf; }
    float4 fb; float lb, rb;
    if (y + 1 < Hh) {
        const float* rowb = rowc + Ww;
        fb = *(const float4*)(rowb + x4);
        lb = (x4 > 0)      ? rowb[x4 - 1] : ninf;
        rb = (x4 + 4 < Ww) ? rowb[x4 + 4] : ninf;
    } else { fb = make_float4(ninf, ninf, ninf, ninf); lb = rb = ninf; }

    float cm0 = fmax3(la, lc, lb);
    float cm1 = fmax3(fa.x, f.x, fb.x);
    float cm2 = fmax3(fa.y, f.y, fb.y);
    float cm3 = fmax3(fa.z, f.z, fb.z);
    float cm4 = fmax3(fa.w, f.w, fb.w);
    float cm5 = fmax3(ra, rc, rb);

    if (f.x >= T0F && f.x >= fmax3(cm0, cm1, cm2)) mb |= 1u;
    if (f.y >= T0F && f.y >= fmax3(cm1, cm2, cm3)) mb |= 2u;
    if (f.z >= T0F && f.z >= fmax3(cm2, cm3, cm4)) mb |= 4u;
    if (f.w >= T0F && f.w >= fmax3(cm3, cm4, cm5)) mb |= 8u;
    return mb;
}

// ---------------- kernel 1: batched-load 3x3 NMS, 4 quads/thread ----------------
__global__ void __launch_bounds__(NMS_T, 3)
nms_collect(const float* __restrict__ hm) {
    __shared__ int wsum[NWARP];
    __shared__ int wbase[NWARP];
    __shared__ int s_gbase;

    int tid = threadIdx.x;
    unsigned lane = tid & 31u;
    int wid = tid >> 5;

    int slice = blockIdx.y;
    int q0    = blockIdx.x * CHUNK + tid;      // quads q0 + i*NMS_T, i in [0,4)
    const float* base = hm + (size_t)slice * HWsz;

    // phase 1: batch all 4 independent 128-bit loads (MLP = 4)
    float4 f[QPT];
#pragma unroll
    for (int i = 0; i < QPT; i++) {
        int q  = q0 + i * NMS_T;
        int y  = q / QPR;
        int x4 = (q - y * QPR) * 4;
        f[i] = *(const float4*)(base + y * Ww + x4);
    }

    // phase 2: branchless filter mask
    unsigned fm = 0;
#pragma unroll
    for (int i = 0; i < QPT; i++) {
        float qm = fmaxf(fmaxf(f[i].x, f[i].y), fmaxf(f[i].z, f[i].w));
        if (qm >= T0F) fm |= 1u << i;
    }

    // phase 3: rare full 3x3 checks (values already in registers)
    unsigned mask16 = 0;
    if (fm) {
#pragma unroll
        for (int i = 0; i < QPT; i++) {
            if (fm & (1u << i)) {
                int q  = q0 + i * NMS_T;
                int y  = q / QPR;
                int x4 = (q - y * QPR) * 4;
                mask16 |= nms_quad(base + y * Ww, f[i], y, x4) << (i * 4);
            }
        }
    }

    int cnt = __popc(mask16);

    // block-wide exclusive scan (order canonicalized later by the full sort)
    int inc = cnt;
#pragma unroll
    for (int d = 1; d < 32; d <<= 1) {
        int o = __shfl_up_sync(0xffffffffu, inc, d);
        if ((int)lane >= d) inc += o;
    }
    if (lane == 31) wsum[wid] = inc;
    __syncthreads();
    if (wid == 0) {
        int s = (lane < NWARP) ? wsum[lane] : 0;
#pragma unroll
        for (int d = 1; d < NWARP; d <<= 1) {
            int o = __shfl_up_sync(0xffffffffu, s, d);
            if ((int)lane >= d) s += o;
        }
        if (lane < NWARP) wbase[lane] = s - wsum[lane];
        if (lane == NWARP - 1) s_gbase = s ? atomicAdd(&g_cnt[slice], s) : 0;
    }
    __syncthreads();

    if (mask16) {
        int off = s_gbase + wbase[wid] + (inc - cnt);
        ull* dst = g_cand + (size_t)slice * HWsz;
#pragma unroll
        for (int i = 0; i < QPT; i++) {
            unsigned mb = (mask16 >> (i * 4)) & 0xFu;
            if (!mb) continue;
            int q  = q0 + i * NMS_T;
            int y  = q / QPR;
            int x4 = (q - y * QPR) * 4;
            unsigned pbase = (unsigned)(y * Ww + x4);
            if (mb & 1u) dst[off++] = make_key(f[i].x, pbase + 0);
            if (mb & 2u) dst[off++] = make_key(f[i].y, pbase + 1);
            if (mb & 4u) dst[off++] = make_key(f[i].z, pbase + 2);
            if (mb & 8u) dst[off++] = make_key(f[i].w, pbase + 3);
        }
    }
}

// ---------------- bitonic sort (descending) ----------------
template <int M>
__device__ void bitonic_desc(ull* buf, int tid, int nt) {
    for (int k = 2; k <= M; k <<= 1) {
        for (int j = k >> 1; j > 0; j >>= 1) {
            for (int i = tid; i < M; i += nt) {
                int ij = i ^ j;
                if (ij > i) {
                    bool dir = ((i & k) == 0);          // true -> descending segment
                    ull a = buf[i], b = buf[ij];
                    if ((a < b) == dir) { buf[i] = b; buf[ij] = a; }
                }
            }
            __syncthreads();
        }
    }
}

// ---------------- kernel 2: per-slice exact top-100, leveled 12-bit radix ----------------
__global__ void select_topk(const float* __restrict__ hm) {
    __shared__ int hist[4096];
    __shared__ ull buf[2048];
    __shared__ int wsc[NWARP];
    __shared__ int s_bin, s_pre, s_mexp, s_m;

    int bc  = blockIdx.x;
    int tid = threadIdx.x;
    const int nt = 512;
    unsigned lane = tid & 31u;
    int wid = tid >> 5;

    int n = g_cnt[bc];
    ull* cand = g_cand + (size_t)bc * HWsz;

    // ---- exact fallback: too few fast candidates -> rebuild ALL survivors inline.
    // (Never executes for this input: fast count ~3.1K >> 100.)
    if (n < KDET) {
        if (tid == 0) s_m = 0;
        __syncthreads();
        const float* base = hm + (size_t)bc * HWsz;
        for (int p = tid; p < HWsz; p += nt) {
            float v = base[p];
            int y = p / Ww, x = p - y * Ww;
            bool sv = true;
#pragma unroll
            for (int dy = -1; dy <= 1; dy++)
#pragma unroll
                for (int dx = -1; dx <= 1; dx++) {
                    if ((dy | dx) == 0) continue;
                    int yy = y + dy, xx = x + dx;
                    if ((unsigned)yy < (unsigned)Hh && (unsigned)xx < (unsigned)Ww)
                        sv = sv && (v >= base[yy * Ww + xx]);
                }
            if (sv) { int o = atomicAdd(&s_m, 1); cand[o] = make_key(v, (unsigned)p); }
        }
        __syncthreads();
        n = s_m;
        __syncthreads();
    }
    if (tid == 0) s_m = 0;

    // ---- leveled 12-bit radix: find pref with |{k >= pref}| in [K, 2048]
    ull pref = 0;
    int prevcum = 0;
    int shift = 52;
#pragma unroll 1
    for (int level = 0; level < 4; level++) {
        for (int i = tid; i < 4096; i += nt) hist[i] = 0;
        if (tid == 0) { s_bin = 0; s_pre = prevcum; s_mexp = prevcum; }
        __syncthreads();

        bool top = (level == 0);
        for (int i = tid; i < n; i += nt) {
            ull k = cand[i];
            if (top || ((k >> (shift + 12)) == (pref >> (shift + 12))))
                atomicAdd(&hist[(int)((k >> shift) & 4095)], 1);
        }
        __syncthreads();

        // parallel suffix scan: thread t owns descending chunk of 8 bins
        int lo = 4096 - 8 * (tid + 1);
        int cs = 0;
#pragma unroll
        for (int j = 0; j < 8; j++) cs += hist[lo + j];
        int inc = cs;
#pragma unroll
        for (int d = 1; d < 32; d <<= 1) {
            int o = __shfl_up_sync(0xffffffffu, inc, d);
            if ((int)lane >= d) inc += o;
        }
        if (lane == 31) wsc[wid] = inc;
        __syncthreads();
        int wpre = 0;
        {
            int s = (lane < NWARP) ? wsc[lane] : 0;
#pragma unroll
            for (int d = 1; d < NWARP; d <<= 1) {
                int o = __shfl_up_sync(0xffffffffu, s, d);
                if ((int)lane >= d) s += o;
            }
            s = __shfl_sync(0xffffffffu, s, (wid == 0) ? 0 : (wid - 1));
            wpre = (wid == 0) ? 0 : s;
        }
        int pre = prevcum + wpre + (inc - cs);
        if (pre < KDET && pre + cs >= KDET) {     // exactly one crossing thread
            int cum = pre;
            for (int j = 7; j >= 0; j--) {
                int bin = lo + j;
                int c = hist[bin];
                if (cum + c >= KDET) { s_bin = bin; s_pre = cum; s_mexp = cum + c; break; }
                cum += c;
            }
        }
        __syncthreads();
        pref |= ((ull)s_bin) << shift;
        prevcum = s_pre;
        int mexp = s_mexp;
        __syncthreads();
        if (mexp <= 2048 || shift == 16) break;
        shift -= 12;
    }

    // ---- single collect pass + sort
    for (int i = tid; i < n; i += nt) {
        ull k = cand[i];
        if (k >= pref) {
            int p = atomicAdd(&s_m, 1);
            if (p < 2048) buf[p] = k;
        }
    }
    __syncthreads();
    int m = min(s_m, 2048);

    if (m <= 512) {
        for (int i = tid + m; i < 512; i += nt) buf[i] = 0xFFFFFFFFull;  // value 0, pix 0
        __syncthreads();
        bitonic_desc<512>(buf, tid, nt);
    } else {
        for (int i = tid + m; i < 2048; i += nt) buf[i] = 0xFFFFFFFFull;
        __syncthreads();
        bitonic_desc<2048>(buf, tid, nt);
    }

    if (tid < KDET) g_top1[bc * KDET + tid] = buf[tid];

    // epilogue: reset counter for the next graph replay
    if (tid == 0) g_cnt[bc] = 0;
}

// ---------------- kernel 3: per-batch 3-way merge-rank + geometry epilogue ----------------
// Three per-class top-100 lists are sorted descending. Global rank of candidate i =
// own index + (# strictly-greater keys in the other lists via binary search). Re-keyed
// 64-bit keys are pairwise distinct => ranks form a permutation == jax top_k order.
__global__ void finalize(const float* __restrict__ reg,
                         const float* __restrict__ trans,
                         const float* __restrict__ Kmat,
                         const float* __restrict__ size2,
                         const float* __restrict__ hcam,
                         const float* __restrict__ dimsIn,
                         float* __restrict__ out) {
    __shared__ ull s_key[3 * KDET];

    int b = blockIdx.x, tid = threadIdx.x;

    unsigned pix = 0;
    if (tid < 3 * KDET) {
        ull k1 = g_top1[b * (3 * KDET) + tid];   // tid = c*100 + j
        pix = 0xFFFFFFFFu - (unsigned)(k1 & 0xFFFFFFFFu);
        if (pix >= (unsigned)HWsz) pix = 0;
        // re-key with flattened C*K position for the second-stage tie-break
        s_key[tid] = (k1 & 0xFFFFFFFF00000000ull) |
                     (ull)(0xFFFFFFFFu - (unsigned)tid);
    }
    __syncthreads();

    if (tid < 3 * KDET) {
        // own regression gathers (issued early; high MLP overlaps the ranking)
        const float* rb = reg + (size_t)b * 4 * HWsz;
        float dv_delta = rb[0 * HWsz + pix];
        float off_u    = rb[1 * HWsz + pix];
        float ori0     = rb[2 * HWsz + pix];
        float ori1     = rb[3 * HWsz + pix];

        ull x = s_key[tid];
        int a = tid / KDET;
        int r = tid - a * KDET;                  // own-list index
#pragma unroll
        for (int L = 0; L < 3; L++) {
            if (L == a) continue;
            const ull* Ls = s_key + L * KDET;
            int lo = 0, hi = KDET;
            while (lo < hi) {                    // count of keys > x (descending list)
                int mid = (lo + hi) >> 1;
                if (Ls[mid] > x) lo = mid + 1; else hi = mid;
            }
            r += lo;
        }

        if (r < KDET) {
            float score = __uint_as_float((unsigned)(x >> 32));
            int clsI = a;

            int ysI = pix / Ww;
            int xsI = pix - ysI * Ww;
            float xs = (float)xsI, ys = (float)ysI;

            // 3x3 inverse of trans_mat (first row needed for img_x)
            const float* T = trans + b * 9;
            float a00=T[0],a01=T[1],a02=T[2],a10=T[3],a11=T[4],a12=T[5],a20=T[6],a21=T[7],a22=T[8];
            float det = a00*(a11*a22 - a12*a21) - a01*(a10*a22 - a12*a20) + a02*(a10*a21 - a11*a20);
            float id = 1.0f / det;
            float i00=(a11*a22-a12*a21)*id, i01=(a02*a21-a01*a22)*id, i02=(a01*a12-a02*a11)*id;

            float ptx = xs + off_u, pty = ys;
            float img_x = i00*ptx + i01*pty + i02;

            const float* Km = Kmat + b * 9;
            float fx = Km[0], cxk = Km[2], fy = Km[4];

            float h = hcam[b];
            float d0 = dimsIn[b*3+0], d1 = dimsIn[b*3+1], d2 = dimsIn[b*3+2];
            if (!isfinite(d0)) d0 = 3.88f;
            if (!isfinite(d1)) d1 = 1.63f;
            if (!isfinite(d2)) d2 = 1.53f;

            float h_ref = h - d1 * 0.5f;
            float fyh = fy * fabsf(h_ref);
            float log_dv_ref = logf(fmaxf(fyh, 1e-7f) / 28.01f);
            float log_dv = fminf(fmaxf(log_dv_ref + dv_delta, -4.0f), 8.0f);
            float depth = fminf(fmaxf(fyh * expf(-log_dv), 0.5f), 120.0f);
            float pxl = (img_x - cxk) * depth / fx;

            float ray = atanf(pxl / (depth + 1e-7f));
            float alpha = atanf(ori0 / (ori1 + 1e-7f)) + (ori1 >= 0.0f ? -HALF_PI_F : HALF_PI_F);
            float roty = alpha + ray;
            if (roty >  PI_F) roty -= 2.0f * PI_F;
            if (roty < -PI_F) roty += 2.0f * PI_F;
            float cs = cosf(roty), sn = sinf(roty);

            const float cx8[8] = {-0.5f, 0.5f, 0.5f, 0.5f, 0.5f,-0.5f,-0.5f,-0.5f};
            const float cy8[8] = {-1.0f,-1.0f, 0.0f, 0.0f,-1.0f,-1.0f, 0.0f, 0.0f};
            const float cz8[8] = {-0.5f,-0.5f,-0.5f, 0.5f, 0.5f, 0.5f, 0.5f,-0.5f};

            float umin =  3.4e38f, umax = -3.4e38f, vmin = 3.4e38f, vmax = -3.4e38f;
#pragma unroll
            for (int i = 0; i < 8; i++) {
                float xc = d0 * cx8[i], yc = d1 * cy8[i], zc = d2 * cz8[i];
                float bx =  cs * xc + sn * zc + pxl;
                float by =  yc + h;
                float bz = -sn * xc + cs * zc + depth;
                float up = Km[0]*bx + Km[1]*by + Km[2]*bz;
                float vp = Km[3]*bx + Km[4]*by + Km[5]*bz;
                float wp = Km[6]*bx + Km[7]*by + Km[8]*bz;
                float u = up / wp, v = vp / wp;
                umin = fminf(umin, u); umax = fmaxf(umax, u);
                vmin = fminf(vmin, v); vmax = fmaxf(vmax, v);
            }
            float img_w = size2[0], img_h = size2[1];
            float xmin = fminf(fmaxf(umin, 0.0f), img_w);
            float xmax = fminf(fmaxf(umax, 0.0f), img_w);
            float ymin = fminf(fmaxf(vmin, 0.0f), img_h);
            float ymax = fminf(fmaxf(vmax, 0.0f), img_h);

            float keep = (score > 0.25f) ? 1.0f : 0.0f;

            float o[14];
            o[0]  = (float)clsI;
            o[1]  = alpha;
            o[2]  = xmin; o[3] = ymin; o[4] = xmax; o[5] = ymax;
            o[6]  = d1;   o[7] = d2;   o[8] = d0;          // roll(dims, -1)
            o[9]  = pxl;  o[10] = h;   o[11] = depth;
            o[12] = roty;
            o[13] = score;

            float* dst = out + (size_t)(b * KDET + r) * 14;
#pragma unroll
            for (int c = 0; c < 14; c++) dst[c] = o[c] * keep;
        }
    }
}

// ---------------- launch ----------------
extern "C" void kernel_launch(void* const* d_in, const int* in_sizes, int n_in,
                              void* d_out, int out_size) {
    const float* hm    = (const float*)d_in[0];
    const float* reg   = (const float*)d_in[1];
    const float* trans = (const float*)d_in[2];
    const float* Kmat  = (const float*)d_in[3];
    const float* size2 = (const float*)d_in[4];
    const float* hcam  = (const float*)d_in[5];
    const float* dims  = (const float*)d_in[6];
    float* out = (float*)d_out;

    dim3 grid(BLK_PER_SLICE, BC);              // (26, 96)
    nms_collect<<<grid, NMS_T>>>(hm);
    select_topk<<<BC, 512>>>(hm);
    finalize<<<Bb, 320>>>(reg, trans, Kmat, size2, hcam, dims, out);
}

// round 17
// speedup vs baseline: 1.1767x; 1.0423x over previous
#include <cuda_runtime.h>
#include <math.h>

typedef unsigned long long ull;

// Problem constants (fixed shapes)
#define Bb 32
#define Cc 3
#define Hh 256
#define Ww 832
#define HWsz (Hh*Ww)          // 212992
#define BC (Bb*Cc)            // 96
#define KDET 100
#define QPR (Ww/4)            // 208 float4-quads per row
#define QPS (Hh*QPR)          // 53248 quads per slice

#define NMS_T 512
#define NWARP (NMS_T / 32)    // 16
#define QPT 4                 // quads per thread
#define CHUNK (NMS_T * QPT)   // 2048 quads per block
#define BLK_PER_SLICE (QPS / CHUNK)   // 26

// Fast-path value filter: survivors below T0F cannot be in the per-slice top-100
// WHENEVER the count of survivors >= T0F is itself >= 100 (all kept keys dominate
// all dropped keys). select_topk verifies the count and falls back to an exact
// full rebuild otherwise. For this input: ~3.1K >= T0F per slice vs K=100 (31x).
#define T0F 0.984375f

#define PI_F 3.14159265358979323846f
#define HALF_PI_F 1.57079632679489661923f

// ---------------- scratch (device globals; no runtime allocation) ----------------
__device__ ull g_cand[(size_t)BC * HWsz];     // per-slice contiguous candidate list
__device__ int g_cnt[BC];                     // per-slice count (reset by select epilogue)
__device__ ull g_top1[BC * KDET];             // per-(b,c) top-100 keys

// key layout: [63:32] = float bits of value (value >= 0 so monotonic as uint)
//             [31:0]  = 0xFFFFFFFF - pixel_index  (larger = smaller index)
// descending key order == jax top_k order (desc value, stable lower-index-first)
__device__ __forceinline__ ull make_key(float v, unsigned pix) {
    return ((ull)__float_as_uint(v) << 32) | (ull)(0xFFFFFFFFu - pix);
}

__device__ __forceinline__ float fmax3(float a, float b, float c) {
    return fmaxf(a, fmaxf(b, c));
}

// 3x3 NMS check for one quad at (y, x4); returns 4-bit survivor mask.
__device__ __forceinline__ unsigned nms_quad(const float* __restrict__ rowc,
                                             float4 f, int y, int x4) {
    const float ninf = __int_as_float(0xff800000);
    unsigned mb = 0;
    float lc = (x4 > 0)      ? rowc[x4 - 1] : ninf;
    float rc = (x4 + 4 < Ww) ? rowc[x4 + 4] : ninf;
    float4 fa; float la, ra;
    if (y > 0) {
        const float* rowa = rowc - Ww;
        fa = *(const float4*)(rowa + x4);
        la = (x4 > 0)      ? rowa[x4 - 1] : ninf;
        ra = (x4 + 4 < Ww) ? rowa[x4 + 4] : ninf;
    } else { fa = make_float4(ninf, ninf, ninf, ninf); la = ra = ninf; }
    float4 fb; float lb, rb;
    if (y + 1 < Hh) {
        const float* rowb = rowc + Ww;
        fb = *(const float4*)(rowb + x4);
        lb = (x4 > 0)      ? rowb[x4 - 1] : ninf;
        rb = (x4 + 4 < Ww) ? rowb[x4 + 4] : ninf;
    } else { fb = make_float4(ninf, ninf, ninf, ninf); lb = rb = ninf; }

    float cm0 = fmax3(la, lc, lb);
    float cm1 = fmax3(fa.x, f.x, fb.x);
    float cm2 = fmax3(fa.y, f.y, fb.y);
    float cm3 = fmax3(fa.z, f.z, fb.z);
    float cm4 = fmax3(fa.w, f.w, fb.w);
    float cm5 = fmax3(ra, rc, rb);

    if (f.x >= T0F && f.x >= fmax3(cm0, cm1, cm2)) mb |= 1u;
    if (f.y >= T0F && f.y >= fmax3(cm1, cm2, cm3)) mb |= 2u;
    if (f.z >= T0F && f.z >= fmax3(cm2, cm3, cm4)) mb |= 4u;
    if (f.w >= T0F && f.w >= fmax3(cm3, cm4, cm5)) mb |= 8u;
    return mb;
}

// ---------------- kernel 1: filter + warp-compacted 3x3 NMS ----------------
// Each warp owns 128 consecutive-strided quads; filter-passing quads (~8/warp)
// are redistributed one-per-lane so the expensive 3x3 check runs ONCE per warp
// with dense lanes instead of 4x with ~2/32 lanes active.
__global__ void __launch_bounds__(NMS_T, 3)
nms_collect(const float* __restrict__ hm) {
    const unsigned FULL = 0xffffffffu;
    int tid = threadIdx.x;
    unsigned lane = tid & 31u;
    int wid = tid >> 5;

    int slice = blockIdx.y;
    int q0    = blockIdx.x * CHUNK + tid;      // quads q0 + i*NMS_T, i in [0,4)
    const float* base = hm + (size_t)slice * HWsz;

    // phase 1: batch all 4 independent 128-bit loads (MLP = 4)
    float4 f[QPT];
#pragma unroll
    for (int i = 0; i < QPT; i++) {
        int q  = q0 + i * NMS_T;
        int y  = q / QPR;
        int x4 = (q - y * QPR) * 4;
        f[i] = *(const float4*)(base + y * Ww + x4);
    }

    // phase 2: filter mask + per-slot ballots
    unsigned fm = 0;
#pragma unroll
    for (int i = 0; i < QPT; i++) {
        float qm = fmaxf(fmaxf(f[i].x, f[i].y), fmaxf(f[i].z, f[i].w));
        if (qm >= T0F) fm |= 1u << i;
    }
    unsigned bal[QPT];
#pragma unroll
    for (int i = 0; i < QPT; i++) bal[i] = __ballot_sync(FULL, (fm >> i) & 1u);

    int c0 = __popc(bal[0]);
    int c1 = c0 + __popc(bal[1]);
    int c2 = c1 + __popc(bal[2]);
    int tot = c2 + __popc(bal[3]);
    if (tot == 0) return;

    int wq0 = blockIdx.x * CHUNK + wid * 32;   // warp's base quad
    ull* dst = g_cand + (size_t)slice * HWsz;

    int iters = (tot + 31) >> 5;               // ==1 in practice
    for (int it = 0; it < iters; it++) {
        int t = it * 32 + (int)lane;
        unsigned mask4 = 0;
        unsigned pbase = 0;
        const float* rowc = 0;
        if (t < tot) {
            int i, L;
            if (t < c0)      { i = 0; L = __fns(bal[0], 0, t + 1); }
            else if (t < c1) { i = 1; L = __fns(bal[1], 0, t - c0 + 1); }
            else if (t < c2) { i = 2; L = __fns(bal[2], 0, t - c1 + 1); }
            else             { i = 3; L = __fns(bal[3], 0, t - c2 + 1); }
            int q  = wq0 + L + i * NMS_T;
            int y  = q / QPR;
            int x4 = (q - y * QPR) * 4;
            rowc = base + y * Ww;
            pbase = (unsigned)(y * Ww + x4);
            float4 fc = *(const float4*)(rowc + x4);   // L1 hit
            mask4 = nms_quad(rowc, fc, y, x4);
        }

        int cnt = __popc(mask4);
        int inc = cnt;
#pragma unroll
        for (int d = 1; d < 32; d <<= 1) {
            int o = __shfl_up_sync(FULL, inc, d);
            if ((int)lane >= d) inc += o;
        }
        int wtot = __shfl_sync(FULL, inc, 31);
        int basei = 0;
        if (lane == 0 && wtot) basei = atomicAdd(&g_cnt[slice], wtot);
        basei = __shfl_sync(FULL, basei, 0);
        int off = basei + inc - cnt;
        while (mask4) {
            int j = __ffs(mask4) - 1; mask4 &= mask4 - 1;
            float v = rowc[(pbase % Ww) + j];            // L1 hit
            dst[off++] = make_key(v, pbase + j);
        }
    }
}

// ---------------- bitonic sort (descending) ----------------
template <int M>
__device__ void bitonic_desc(ull* buf, int tid, int nt) {
    for (int k = 2; k <= M; k <<= 1) {
        for (int j = k >> 1; j > 0; j >>= 1) {
            for (int i = tid; i < M; i += nt) {
                int ij = i ^ j;
                if (ij > i) {
                    bool dir = ((i & k) == 0);          // true -> descending segment
                    ull a = buf[i], b = buf[ij];
                    if ((a < b) == dir) { buf[i] = b; buf[ij] = a; }
                }
            }
            __syncthreads();
        }
    }
}

// ---------------- kernel 2: per-slice exact top-100, leveled 12-bit radix ----------------
__global__ void select_topk(const float* __restrict__ hm) {
    __shared__ int hist[4096];
    __shared__ ull buf[2048];
    __shared__ int wsc[NWARP];
    __shared__ int s_bin, s_pre, s_mexp, s_m;

    int bc  = blockIdx.x;
    int tid = threadIdx.x;
    const int nt = 512;
    unsigned lane = tid & 31u;
    int wid = tid >> 5;

    int n = g_cnt[bc];
    ull* cand = g_cand + (size_t)bc * HWsz;

    // ---- exact fallback: too few fast candidates -> rebuild ALL survivors inline.
    // (Never executes for this input: fast count ~3.1K >> 100.)
    if (n < KDET) {
        if (tid == 0) s_m = 0;
        __syncthreads();
        const float* base = hm + (size_t)bc * HWsz;
        for (int p = tid; p < HWsz; p += nt) {
            float v = base[p];
            int y = p / Ww, x = p - y * Ww;
            bool sv = true;
#pragma unroll
            for (int dy = -1; dy <= 1; dy++)
#pragma unroll
                for (int dx = -1; dx <= 1; dx++) {
                    if ((dy | dx) == 0) continue;
                    int yy = y + dy, xx = x + dx;
                    if ((unsigned)yy < (unsigned)Hh && (unsigned)xx < (unsigned)Ww)
                        sv = sv && (v >= base[yy * Ww + xx]);
                }
            if (sv) { int o = atomicAdd(&s_m, 1); cand[o] = make_key(v, (unsigned)p); }
        }
        __syncthreads();
        n = s_m;
        __syncthreads();
    }
    if (tid == 0) s_m = 0;

    // ---- leveled 12-bit radix: find pref with |{k >= pref}| in [K, 2048]
    ull pref = 0;
    int prevcum = 0;
    int shift = 52;
#pragma unroll 1
    for (int level = 0; level < 4; level++) {
        for (int i = tid; i < 4096; i += nt) hist[i] = 0;
        if (tid == 0) { s_bin = 0; s_pre = prevcum; s_mexp = prevcum; }
        __syncthreads();

        bool top = (level == 0);
        for (int i = tid; i < n; i += nt) {
            ull k = cand[i];
            if (top || ((k >> (shift + 12)) == (pref >> (shift + 12))))
                atomicAdd(&hist[(int)((k >> shift) & 4095)], 1);
        }
        __syncthreads();

        // parallel suffix scan: thread t owns descending chunk of 8 bins
        int lo = 4096 - 8 * (tid + 1);
        int cs = 0;
#pragma unroll
        for (int j = 0; j < 8; j++) cs += hist[lo + j];
        int inc = cs;
#pragma unroll
        for (int d = 1; d < 32; d <<= 1) {
            int o = __shfl_up_sync(0xffffffffu, inc, d);
            if ((int)lane >= d) inc += o;
        }
        if (lane == 31) wsc[wid] = inc;
        __syncthreads();
        int wpre = 0;
        {
            int s = (lane < NWARP) ? wsc[lane] : 0;
#pragma unroll
            for (int d = 1; d < NWARP; d <<= 1) {
                int o = __shfl_up_sync(0xffffffffu, s, d);
                if ((int)lane >= d) s += o;
            }
            s = __shfl_sync(0xffffffffu, s, (wid == 0) ? 0 : (wid - 1));
            wpre = (wid == 0) ? 0 : s;
        }
        int pre = prevcum + wpre + (inc - cs);
        if (pre < KDET && pre + cs >= KDET) {     // exactly one crossing thread
            int cum = pre;
            for (int j = 7; j >= 0; j--) {
                int bin = lo + j;
                int c = hist[bin];
                if (cum + c >= KDET) { s_bin = bin; s_pre = cum; s_mexp = cum + c; break; }
                cum += c;
            }
        }
        __syncthreads();
        pref |= ((ull)s_bin) << shift;
        prevcum = s_pre;
        int mexp = s_mexp;
        __syncthreads();
        if (mexp <= 2048 || shift == 16) break;
        shift -= 12;
    }

    // ---- single collect pass + sort
    for (int i = tid; i < n; i += nt) {
        ull k = cand[i];
        if (k >= pref) {
            int p = atomicAdd(&s_m, 1);
            if (p < 2048) buf[p] = k;
        }
    }
    __syncthreads();
    int m = min(s_m, 2048);

    if (m <= 512) {
        for (int i = tid + m; i < 512; i += nt) buf[i] = 0xFFFFFFFFull;  // value 0, pix 0
        __syncthreads();
        bitonic_desc<512>(buf, tid, nt);
    } else {
        for (int i = tid + m; i < 2048; i += nt) buf[i] = 0xFFFFFFFFull;
        __syncthreads();
        bitonic_desc<2048>(buf, tid, nt);
    }

    if (tid < KDET) g_top1[bc * KDET + tid] = buf[tid];

    // epilogue: reset counter for the next graph replay
    if (tid == 0) g_cnt[bc] = 0;
}

// ---------------- kernel 3: per-batch 3-way merge-rank + geometry epilogue ----------------
// Three per-class top-100 lists are sorted descending. Global rank of candidate i =
// own index + (# strictly-greater keys in the other lists via binary search). Re-keyed
// 64-bit keys are pairwise distinct => ranks form a permutation == jax top_k order.
__global__ void finalize(const float* __restrict__ reg,
                         const float* __restrict__ trans,
                         const float* __restrict__ Kmat,
                         const float* __restrict__ size2,
                         const float* __restrict__ hcam,
                         const float* __restrict__ dimsIn,
                         float* __restrict__ out) {
    __shared__ ull s_key[3 * KDET];

    int b = blockIdx.x, tid = threadIdx.x;

    unsigned pix = 0;
    if (tid < 3 * KDET) {
        ull k1 = g_top1[b * (3 * KDET) + tid];   // tid = c*100 + j
        pix = 0xFFFFFFFFu - (unsigned)(k1 & 0xFFFFFFFFu);
        if (pix >= (unsigned)HWsz) pix = 0;
        // re-key with flattened C*K position for the second-stage tie-break
        s_key[tid] = (k1 & 0xFFFFFFFF00000000ull) |
                     (ull)(0xFFFFFFFFu - (unsigned)tid);
    }
    __syncthreads();

    if (tid < 3 * KDET) {
        // own regression gathers (issued early; high MLP overlaps the ranking)
        const float* rb = reg + (size_t)b * 4 * HWsz;
        float dv_delta = rb[0 * HWsz + pix];
        float off_u    = rb[1 * HWsz + pix];
        float ori0     = rb[2 * HWsz + pix];
        float ori1     = rb[3 * HWsz + pix];

        ull x = s_key[tid];
        int a = tid / KDET;
        int r = tid - a * KDET;                  // own-list index
#pragma unroll
        for (int L = 0; L < 3; L++) {
            if (L == a) continue;
            const ull* Ls = s_key + L * KDET;
            int lo = 0, hi = KDET;
            while (lo < hi) {                    // count of keys > x (descending list)
                int mid = (lo + hi) >> 1;
                if (Ls[mid] > x) lo = mid + 1; else hi = mid;
            }
            r += lo;
        }

        if (r < KDET) {
            float score = __uint_as_float((unsigned)(x >> 32));
            int clsI = a;

            int ysI = pix / Ww;
            int xsI = pix - ysI * Ww;
            float xs = (float)xsI, ys = (float)ysI;

            // 3x3 inverse of trans_mat (first row needed for img_x)
            const float* T = trans + b * 9;
            float a00=T[0],a01=T[1],a02=T[2],a10=T[3],a11=T[4],a12=T[5],a20=T[6],a21=T[7],a22=T[8];
            float det = a00*(a11*a22 - a12*a21) - a01*(a10*a22 - a12*a20) + a02*(a10*a21 - a11*a20);
            float id = 1.0f / det;
            float i00=(a11*a22-a12*a21)*id, i01=(a02*a21-a01*a22)*id, i02=(a01*a12-a02*a11)*id;

            float ptx = xs + off_u, pty = ys;
            float img_x = i00*ptx + i01*pty + i02;

            const float* Km = Kmat + b * 9;
            float fx = Km[0], cxk = Km[2], fy = Km[4];

            float h = hcam[b];
            float d0 = dimsIn[b*3+0], d1 = dimsIn[b*3+1], d2 = dimsIn[b*3+2];
            if (!isfinite(d0)) d0 = 3.88f;
            if (!isfinite(d1)) d1 = 1.63f;
            if (!isfinite(d2)) d2 = 1.53f;

            float h_ref = h - d1 * 0.5f;
            float fyh = fy * fabsf(h_ref);
            float log_dv_ref = logf(fmaxf(fyh, 1e-7f) / 28.01f);
            float log_dv = fminf(fmaxf(log_dv_ref + dv_delta, -4.0f), 8.0f);
            float depth = fminf(fmaxf(fyh * expf(-log_dv), 0.5f), 120.0f);
            float pxl = (img_x - cxk) * depth / fx;

            float ray = atanf(pxl / (depth + 1e-7f));
            float alpha = atanf(ori0 / (ori1 + 1e-7f)) + (ori1 >= 0.0f ? -HALF_PI_F : HALF_PI_F);
            float roty = alpha + ray;
            if (roty >  PI_F) roty -= 2.0f * PI_F;
            if (roty < -PI_F) roty += 2.0f * PI_F;
            float cs = cosf(roty), sn = sinf(roty);

            const float cx8[8] = {-0.5f, 0.5f, 0.5f, 0.5f, 0.5f,-0.5f,-0.5f,-0.5f};
            const float cy8[8] = {-1.0f,-1.0f, 0.0f, 0.0f,-1.0f,-1.0f, 0.0f, 0.0f};
            const float cz8[8] = {-0.5f,-0.5f,-0.5f, 0.5f, 0.5f, 0.5f, 0.5f,-0.5f};

            float umin =  3.4e38f, umax = -3.4e38f, vmin = 3.4e38f, vmax = -3.4e38f;
#pragma unroll
            for (int i = 0; i < 8; i++) {
                float xc = d0 * cx8[i], yc = d1 * cy8[i], zc = d2 * cz8[i];
                float bx =  cs * xc + sn * zc + pxl;
                float by =  yc + h;
                float bz = -sn * xc + cs * zc + depth;
                float up = Km[0]*bx + Km[1]*by + Km[2]*bz;
                float vp = Km[3]*bx + Km[4]*by + Km[5]*bz;
                float wp = Km[6]*bx + Km[7]*by + Km[8]*bz;
                float u = up / wp, v = vp / wp;
                umin = fminf(umin, u); umax = fmaxf(umax, u);
                vmin = fminf(vmin, v); vmax = fmaxf(vmax, v);
            }
            float img_w = size2[0], img_h = size2[1];
            float xmin = fminf(fmaxf(umin, 0.0f), img_w);
            float xmax = fminf(fmaxf(umax, 0.0f), img_w);
            float ymin = fminf(fmaxf(vmin, 0.0f), img_h);
            float ymax = fminf(fmaxf(vmax, 0.0f), img_h);

            float keep = (score > 0.25f) ? 1.0f : 0.0f;

            float o[14];
            o[0]  = (float)clsI;
            o[1]  = alpha;
            o[2]  = xmin; o[3] = ymin; o[4] = xmax; o[5] = ymax;
            o[6]  = d1;   o[7] = d2;   o[8] = d0;          // roll(dims, -1)
            o[9]  = pxl;  o[10] = h;   o[11] = depth;
            o[12] = roty;
            o[13] = score;

            float* dst = out + (size_t)(b * KDET + r) * 14;
#pragma unroll
            for (int c = 0; c < 14; c++) dst[c] = o[c] * keep;
        }
    }
}

// ---------------- launch ----------------
extern "C" void kernel_launch(void* const* d_in, const int* in_sizes, int n_in,
                              void* d_out, int out_size) {
    const float* hm    = (const float*)d_in[0];
    const float* reg   = (const float*)d_in[1];
    const float* trans = (const float*)d_in[2];
    const float* Kmat  = (const float*)d_in[3];
    const float* size2 = (const float*)d_in[4];
    const float* hcam  = (const float*)d_in[5];
    const float* dims  = (const float*)d_in[6];
    float* out = (float*)d_out;

    dim3 grid(BLK_PER_SLICE, BC);              // (26, 96)
    nms_collect<<<grid, NMS_T>>>(hm);
    select_topk<<<BC, 512>>>(hm);
    finalize<<<Bb, 320>>>(reg, trans, Kmat, size2, hcam, dims, out);
}